// round 1
// baseline (speedup 1.0000x reference)
#include <cuda_runtime.h>
#include <cstdint>

// Problem constants (fixed by setup_inputs)
static constexpr int B    = 16;
static constexpr int H    = 256;
static constexpr int W    = 256;
static constexpr int CIN0 = 3;
static constexpr int CMID = 16;
static constexpr int COUT = 64;
static constexpr float BN_EPS = 1e-5f;

// Scratch: intermediates + BN stats. __device__ globals (no runtime allocation).
__device__ float g_h1[(size_t)B * CMID * H * W];   // 64 MB
__device__ float g_h2[(size_t)B * CMID * H * W];   // 64 MB
__device__ float g_stats[2 * COUT];                // [0:64) sum, [64:128) sumsq
__device__ float g_scale[COUT];
__device__ float g_shift[COUT];

// ---------------------------------------------------------------------------
// Tiled direct 3x3 conv (pad 1, stride 1), NCHW.
// Block computes a TH x TW output tile for all CO channels of one batch image.
// Thread register tile: 8 consecutive-x pixels  x  8 output channels.
// smem: input tile with halo (CI x (TH+2) x RS) + weights relaid as [k][co]
// so weight loads are warp-uniform (broadcast) LDS.128.
// STATS: fuse BN sum/sumsq accumulation (only valid when NPX == 32, i.e. a
// full warp shares one co-group — true for the conv3 instantiation).
// ---------------------------------------------------------------------------
template <int CI, int CO, int TH, int TW, bool STATS>
__global__ void __launch_bounds__(256, 2)
conv3x3_tile(const float* __restrict__ in, const float* __restrict__ wgt,
             float* __restrict__ out)
{
    constexpr int NT  = 256;
    constexpr int NPX = TH * TW / 8;      // pixel slots (8 px each)
    constexpr int NCG = CO / 8;           // channel groups (8 co each)
    static_assert(NPX * NCG == NT, "thread shape mismatch");
    constexpr int IH = TH + 2;
    constexpr int IW = TW + 2;
    constexpr int RS = (IW + 3) & ~3;     // row stride, 16B-aligned rows

    extern __shared__ float smem[];
    float* s_in = smem;                   // CI * IH * RS floats
    float* s_w  = smem + CI * IH * RS;    // CI * 9 * CO floats, layout [k][co]

    const int tid = threadIdx.x;
    const int tiles_x = W / TW;
    const int tiles_y = H / TH;
    int bid = blockIdx.x;
    const int tx = bid % tiles_x; bid /= tiles_x;
    const int ty = bid % tiles_y; bid /= tiles_y;
    const int b  = bid;

    // Stage weights: global w[co][ci][dy][dx] -> smem s_w[(ci*9+t)*CO + co]
    for (int i = tid; i < CI * 9 * CO; i += NT) {
        const int k  = i / CO;
        const int co = i - k * CO;
        const int ci = k / 9;
        const int t  = k - ci * 9;
        s_w[i] = wgt[(co * CI + ci) * 9 + t];
    }

    // Stage input tile with halo, zero-padded at image borders.
    const float* inb = in + (size_t)b * CI * H * W;
    const int gy0 = ty * TH - 1;
    const int gx0 = tx * TW - 1;
    for (int i = tid; i < CI * IH * IW; i += NT) {
        const int ci = i / (IH * IW);
        int r = i - ci * IH * IW;
        const int y = r / IW;
        const int x = r - y * IW;
        const int gy = gy0 + y, gx = gx0 + x;
        float v = 0.f;
        if (gy >= 0 && gy < H && gx >= 0 && gx < W)
            v = inb[(ci * H + gy) * W + gx];
        s_in[(ci * IH + y) * RS + x] = v;
    }
    __syncthreads();

    const int px_slot = tid % NPX;            // warp-uniform co-group layout
    const int cg      = tid / NPX;
    const int py      = px_slot / (TW / 8);
    const int x0      = (px_slot - py * (TW / 8)) * 8;
    const int co0     = cg * 8;

    float acc[8][8];                           // [co][px]
    #pragma unroll
    for (int i = 0; i < 8; ++i)
        #pragma unroll
        for (int j = 0; j < 8; ++j) acc[i][j] = 0.f;

    #pragma unroll 1                           // keep code size I$-friendly
    for (int ci = 0; ci < CI; ++ci) {
        #pragma unroll
        for (int dy = 0; dy < 3; ++dy) {
            // Load the 10-wide input row once; reuse across dx and all co.
            const float* rowp = &s_in[(ci * IH + py + dy) * RS + x0];
            float rr[10];
            const float4 a0 = *reinterpret_cast<const float4*>(rowp);
            const float4 a1 = *reinterpret_cast<const float4*>(rowp + 4);
            const float2 a2 = *reinterpret_cast<const float2*>(rowp + 8);
            rr[0] = a0.x; rr[1] = a0.y; rr[2] = a0.z; rr[3] = a0.w;
            rr[4] = a1.x; rr[5] = a1.y; rr[6] = a1.z; rr[7] = a1.w;
            rr[8] = a2.x; rr[9] = a2.y;
            #pragma unroll
            for (int dx = 0; dx < 3; ++dx) {
                const float* wp = &s_w[(ci * 9 + dy * 3 + dx) * CO + co0];
                const float4 w0 = *reinterpret_cast<const float4*>(wp);
                const float4 w1 = *reinterpret_cast<const float4*>(wp + 4);
                const float wv[8] = {w0.x, w0.y, w0.z, w0.w,
                                     w1.x, w1.y, w1.z, w1.w};
                #pragma unroll
                for (int co = 0; co < 8; ++co)
                    #pragma unroll
                    for (int px = 0; px < 8; ++px)
                        acc[co][px] = fmaf(wv[co], rr[px + dx], acc[co][px]);
            }
        }
    }

    // Store: 8 co rows x 8 contiguous px (two float4 each).
    float* outb = out + (size_t)b * CO * H * W;
    const int oy = ty * TH + py;
    const int ox = tx * TW + x0;
    #pragma unroll
    for (int co = 0; co < 8; ++co) {
        float* op = &outb[((size_t)(co0 + co) * H + oy) * W + ox];
        *reinterpret_cast<float4*>(op) =
            make_float4(acc[co][0], acc[co][1], acc[co][2], acc[co][3]);
        *reinterpret_cast<float4*>(op + 4) =
            make_float4(acc[co][4], acc[co][5], acc[co][6], acc[co][7]);
    }

    if (STATS) {
        // Entire warp shares one co-group (NPX == 32): shuffle-reduce per co.
        #pragma unroll
        for (int co = 0; co < 8; ++co) {
            float s = 0.f, q = 0.f;
            #pragma unroll
            for (int px = 0; px < 8; ++px) {
                s += acc[co][px];
                q = fmaf(acc[co][px], acc[co][px], q);
            }
            #pragma unroll
            for (int off = 16; off > 0; off >>= 1) {
                s += __shfl_xor_sync(0xffffffffu, s, off);
                q += __shfl_xor_sync(0xffffffffu, q, off);
            }
            if ((tid & 31) == 0) {
                atomicAdd(&g_stats[co0 + co], s);
                atomicAdd(&g_stats[COUT + co0 + co], q);
            }
        }
    }
}

__global__ void zero_stats_kernel()
{
    if (threadIdx.x < 2 * COUT) g_stats[threadIdx.x] = 0.f;
}

__global__ void bn_finalize_kernel(const float* __restrict__ gamma,
                                   const float* __restrict__ beta)
{
    const int c = threadIdx.x;
    if (c >= COUT) return;
    const float n    = (float)B * (float)H * (float)W;  // 1,048,576
    const float mean = g_stats[c] / n;
    const float var  = g_stats[COUT + c] / n - mean * mean;
    const float sc   = gamma[c] * rsqrtf(var + BN_EPS);
    g_scale[c] = sc;
    g_shift[c] = beta[c] - mean * sc;
}

// In-place normalize of d_out, vectorized float4. Per channel there are
// 65536/4 = 16384 float4s, so (idx >> 14) & 63 is the channel (block-uniform).
__global__ void bn_apply_kernel(float* __restrict__ out)
{
    const int idx = blockIdx.x * blockDim.x + threadIdx.x;   // float4 index
    const int c = (idx >> 14) & (COUT - 1);
    const float sc = g_scale[c];
    const float sh = g_shift[c];
    float4 v = reinterpret_cast<float4*>(out)[idx];
    v.x = fmaf(v.x, sc, sh);
    v.y = fmaf(v.y, sc, sh);
    v.z = fmaf(v.z, sc, sh);
    v.w = fmaf(v.w, sc, sh);
    reinterpret_cast<float4*>(out)[idx] = v;
}

extern "C" void kernel_launch(void* const* d_in, const int* in_sizes, int n_in,
                              void* d_out, int out_size)
{
    (void)in_sizes; (void)n_in; (void)out_size;
    const float* x     = (const float*)d_in[0];
    const float* w1    = (const float*)d_in[1];
    const float* w2    = (const float*)d_in[2];
    const float* w3    = (const float*)d_in[3];
    const float* gamma = (const float*)d_in[4];
    const float* beta  = (const float*)d_in[5];
    float* out = (float*)d_out;

    float *h1, *h2;
    cudaGetSymbolAddress((void**)&h1, g_h1);
    cudaGetSymbolAddress((void**)&h2, g_h2);

    auto* k1 = conv3x3_tile<CIN0, CMID, 32, 32, false>;
    auto* k2 = conv3x3_tile<CMID, CMID, 32, 32, false>;
    auto* k3 = conv3x3_tile<CMID, COUT, 16, 16, true>;

    constexpr int SM1 = (CIN0 * 34 * 36 + CIN0 * 9 * CMID) * 4;   // 16,416 B
    constexpr int SM2 = (CMID * 34 * 36 + CMID * 9 * CMID) * 4;   // 87,552 B
    constexpr int SM3 = (CMID * 18 * 20 + CMID * 9 * COUT) * 4;   // 59,904 B

    cudaFuncSetAttribute(k1, cudaFuncAttributeMaxDynamicSharedMemorySize, SM1);
    cudaFuncSetAttribute(k2, cudaFuncAttributeMaxDynamicSharedMemorySize, SM2);
    cudaFuncSetAttribute(k3, cudaFuncAttributeMaxDynamicSharedMemorySize, SM3);

    zero_stats_kernel<<<1, 128>>>();
    k1<<<B * (H / 32) * (W / 32), 256, SM1>>>(x,  w1, h1);
    k2<<<B * (H / 32) * (W / 32), 256, SM2>>>(h1, w2, h2);
    k3<<<B * (H / 16) * (W / 16), 256, SM3>>>(h2, w3, out);
    bn_finalize_kernel<<<1, 64>>>(gamma, beta);
    bn_apply_kernel<<<(B * COUT * H * W / 4) / 256, 256>>>(out);
}